// round 1
// baseline (speedup 1.0000x reference)
#include <cuda_runtime.h>

// ---------------- problem constants ----------------
#define D_MODEL 1024
#define Hh      16
#define Nn      4
#define NSKEW   6          // N*(N-1)/2
#define Bb      4
#define Tt      4096
#define NROWS   (Bb*Tt)                    // 16384
#define NCOLS1  (Hh*NSKEW + Hh*Nn)         // 96 + 64 = 160
#define VOFF    (Hh*NSKEW)                 // 96
#define HN      (Hh*Nn)                    // 64
#define CHAINS  (Bb*Hh)                    // 64
#define CHUNK   64
#define NCHUNK  (Tt/CHUNK)                 // 64

// ---------------- scratch (static device memory; no allocs) ----------------
__device__ float g_Wcat[D_MODEL*NCOLS1];        // concat [W_skew | W_v], 1024x160
__device__ float g_SV  [NROWS*NCOLS1];          // x @ Wcat            16384x160
__device__ float g_R   [CHAINS*Tt*16];          // per-step rotations (chain-major)
__device__ float g_L   [CHAINS*Tt*16];          // chunk-local prefix products
__device__ float g_Ctot[CHAINS*NCHUNK*16];      // per-chunk total products
__device__ float g_Pprev[CHAINS*NCHUNK*16];     // exclusive chunk prefixes
__device__ float g_Rot [NROWS*HN];              // rotated values      16384x64

// ---------------- small helpers ----------------
__device__ __forceinline__ void mm4(const float* __restrict__ A,
                                    const float* __restrict__ B,
                                    float* __restrict__ C) {
    // C = A @ B, row-major 4x4 (C must not alias A or B)
    #pragma unroll
    for (int i = 0; i < 4; i++) {
        #pragma unroll
        for (int j = 0; j < 4; j++) {
            C[i*4+j] = A[i*4+0]*B[0*4+j] + A[i*4+1]*B[1*4+j]
                     + A[i*4+2]*B[2*4+j] + A[i*4+3]*B[3*4+j];
        }
    }
}

// ---------------- K0: concat weights ----------------
__global__ void concat_w_kernel(const float* __restrict__ Wskew,
                                const float* __restrict__ Wv) {
    int i = blockIdx.x*blockDim.x + threadIdx.x;
    if (i >= D_MODEL*NCOLS1) return;
    int k = i / NCOLS1, c = i % NCOLS1;
    g_Wcat[i] = (c < VOFF) ? Wskew[k*VOFF + c] : Wv[k*HN + (c - VOFF)];
}

// ---------------- generic fp32 SMEM-tiled GEMM body ----------------
// A: MxK row-major, B: KxN row-major, C: MxN row-major.
// BM=128, BN=32, BK=32, TM=8, TN=4 -> 128 threads/block.
// Requires M%128==0, N%32==0, K%32==0 (true for all uses here).
template<int M, int N, int K>
__device__ __forceinline__ void gemm_body(const float* __restrict__ A,
                                          const float* __restrict__ B,
                                          float* __restrict__ C) {
    constexpr int BM = 128, BN = 32, BK = 32, TM = 8, TN = 4;
    constexpr int THREADS = (BM/TM)*(BN/TN);   // 128
    __shared__ float As[BK][BM];               // transposed tile: As[k][m]
    __shared__ float Bs[BK][BN];

    const int tid  = threadIdx.x;
    const int brow = blockIdx.y * BM;
    const int bcol = blockIdx.x * BN;
    const int tr   = tid / (BN/TN);            // 0..15
    const int tc   = tid % (BN/TN);            // 0..7

    float acc[TM][TN] = {};

    for (int k0 = 0; k0 < K; k0 += BK) {
        // load A tile (BM*BK = 4096 floats, 8 float4 / thread), transpose into As
        #pragma unroll
        for (int i = 0; i < (BM*BK)/(THREADS*4); ++i) {
            int e   = (tid + i*THREADS) * 4;
            int row = e / BK;
            int kk  = e % BK;
            float4 v = *(const float4*)(A + (size_t)(brow+row)*K + k0 + kk);
            As[kk+0][row] = v.x; As[kk+1][row] = v.y;
            As[kk+2][row] = v.z; As[kk+3][row] = v.w;
        }
        // load B tile (BK*BN = 1024 floats, 2 float4 / thread)
        #pragma unroll
        for (int i = 0; i < (BK*BN)/(THREADS*4); ++i) {
            int e   = (tid + i*THREADS) * 4;
            int kk  = e / BN;
            int col = e % BN;
            *(float4*)&Bs[kk][col] =
                *(const float4*)(B + (size_t)(k0+kk)*N + bcol + col);
        }
        __syncthreads();

        #pragma unroll
        for (int kk = 0; kk < BK; ++kk) {
            float a[TM], bv[TN];
            #pragma unroll
            for (int j = 0; j < TN; j++) bv[j] = Bs[kk][tc*TN + j];
            #pragma unroll
            for (int i = 0; i < TM; i++) a[i] = As[kk][tr*TM + i];
            #pragma unroll
            for (int i = 0; i < TM; i++)
                #pragma unroll
                for (int j = 0; j < TN; j++)
                    acc[i][j] += a[i] * bv[j];
        }
        __syncthreads();
    }

    #pragma unroll
    for (int i = 0; i < TM; i++) {
        float4 v = make_float4(acc[i][0], acc[i][1], acc[i][2], acc[i][3]);
        *(float4*)(C + (size_t)(brow + tr*TM + i)*N + bcol + tc*TN) = v;
    }
}

__global__ void gemm1_kernel(const float* __restrict__ x) {
    gemm_body<NROWS, NCOLS1, D_MODEL>(x, g_Wcat, g_SV);
}
__global__ void gemm2_kernel(const float* __restrict__ Wo, float* __restrict__ out) {
    gemm_body<NROWS, D_MODEL, HN>(g_Rot, Wo, out);
}

// ---------------- K2: expm of 4x4 skew-symmetric (scaling & squaring) ----------------
__global__ void expm_kernel() {
    int tid = blockIdx.x*blockDim.x + threadIdx.x;   // chain-major: chain*Tt + t
    if (tid >= CHAINS*Tt) return;
    int t     = tid & (Tt-1);
    int chain = tid >> 12;
    int b     = chain >> 4;
    int h     = chain & 15;
    int n     = b*Tt + t;

    const float* s = g_SV + (size_t)n*NCOLS1 + h*NSKEW;
    float a01 = s[0], a02 = s[1], a03 = s[2], a12 = s[3], a13 = s[4], a23 = s[5];

    float fr = sqrtf(2.0f*(a01*a01 + a02*a02 + a03*a03 +
                           a12*a12 + a13*a13 + a23*a23));
    int sft = 0;
    float f = fr;
    while (f > 0.25f && sft < 32) { f *= 0.5f; sft++; }
    float sc = ldexpf(1.0f, -sft);

    float A[16] = {  0.f,  a01,  a02,  a03,
                    -a01,  0.f,  a12,  a13,
                    -a02, -a12,  0.f,  a23,
                    -a03, -a13, -a23,  0.f };
    #pragma unroll
    for (int e = 0; e < 16; e++) A[e] *= sc;

    // Taylor order 8 via Horner: Tm = I + A(I + A/2(I + ... (I + A/8)))
    float Tm[16], Tmp[16];
    #pragma unroll
    for (int e = 0; e < 16; e++)
        Tm[e] = A[e]*(1.0f/8.0f) + ((e % 5 == 0) ? 1.0f : 0.0f);
    #pragma unroll
    for (int k = 7; k >= 1; k--) {
        mm4(A, Tm, Tmp);
        float inv = 1.0f/(float)k;
        #pragma unroll
        for (int e = 0; e < 16; e++)
            Tm[e] = Tmp[e]*inv + ((e % 5 == 0) ? 1.0f : 0.0f);
    }
    for (int q = 0; q < sft; q++) {
        mm4(Tm, Tm, Tmp);
        #pragma unroll
        for (int e = 0; e < 16; e++) Tm[e] = Tmp[e];
    }

    float4* out = (float4*)(g_R + (size_t)tid*16);
    out[0] = make_float4(Tm[0],  Tm[1],  Tm[2],  Tm[3]);
    out[1] = make_float4(Tm[4],  Tm[5],  Tm[6],  Tm[7]);
    out[2] = make_float4(Tm[8],  Tm[9],  Tm[10], Tm[11]);
    out[3] = make_float4(Tm[12], Tm[13], Tm[14], Tm[15]);
}

// ---------------- K3: chunk-local prefix products ----------------
// 4 threads per (chain, chunk); thread `lane` owns column `lane` of the running
// product M (col' = R @ col -> threads fully independent, no comms needed).
__global__ void scan_local_kernel() {
    int gtid  = blockIdx.x*blockDim.x + threadIdx.x;
    int lane  = gtid & 3;
    int g     = gtid >> 2;                 // group = chain*NCHUNK + chunk
    if (g >= CHAINS*NCHUNK) return;
    int chunk = g & (NCHUNK-1);
    int chain = g >> 6;                    // NCHUNK == 64

    const float4* Rb = (const float4*)(g_R + ((size_t)chain*Tt + chunk*CHUNK)*16);
    float* Lb        = g_L + ((size_t)chain*Tt + chunk*CHUNK)*16;

    float m0 = (lane==0), m1 = (lane==1), m2 = (lane==2), m3 = (lane==3);
    for (int t = 0; t < CHUNK; t++) {
        float4 r0 = Rb[t*4+0], r1 = Rb[t*4+1], r2 = Rb[t*4+2], r3 = Rb[t*4+3];
        float n0 = r0.x*m0 + r0.y*m1 + r0.z*m2 + r0.w*m3;
        float n1 = r1.x*m0 + r1.y*m1 + r1.z*m2 + r1.w*m3;
        float n2 = r2.x*m0 + r2.y*m1 + r2.z*m2 + r2.w*m3;
        float n3 = r3.x*m0 + r3.y*m1 + r3.z*m2 + r3.w*m3;
        m0 = n0; m1 = n1; m2 = n2; m3 = n3;
        Lb[t*16 +  0 + lane] = m0;
        Lb[t*16 +  4 + lane] = m1;
        Lb[t*16 +  8 + lane] = m2;
        Lb[t*16 + 12 + lane] = m3;
    }
    float* Cb = g_Ctot + ((size_t)chain*NCHUNK + chunk)*16;
    Cb[ 0 + lane] = m0; Cb[ 4 + lane] = m1;
    Cb[ 8 + lane] = m2; Cb[12 + lane] = m3;
}

// ---------------- K4: exclusive prefix over chunk totals (64 chains) ----------------
__global__ void prefix_kernel() {
    int tid = threadIdx.x;
    if (tid >= CHAINS*4) return;
    int lane  = tid & 3;
    int chain = tid >> 2;

    const float4* Cb = (const float4*)(g_Ctot + (size_t)chain*NCHUNK*16);
    float p0 = (lane==0), p1 = (lane==1), p2 = (lane==2), p3 = (lane==3);

    float4 r0 = Cb[0], r1 = Cb[1], r2 = Cb[2], r3 = Cb[3];
    for (int c = 0; c < NCHUNK; c++) {
        float4 n0, n1, n2, n3;
        bool more = (c + 1 < NCHUNK);
        if (more) {                               // prefetch next chunk total
            const float4* Nb = Cb + (size_t)(c+1)*4;
            n0 = Nb[0]; n1 = Nb[1]; n2 = Nb[2]; n3 = Nb[3];
        }
        float* Pb = g_Pprev + ((size_t)chain*NCHUNK + c)*16;
        Pb[ 0 + lane] = p0; Pb[ 4 + lane] = p1;
        Pb[ 8 + lane] = p2; Pb[12 + lane] = p3;

        float q0 = r0.x*p0 + r0.y*p1 + r0.z*p2 + r0.w*p3;
        float q1 = r1.x*p0 + r1.y*p1 + r1.z*p2 + r1.w*p3;
        float q2 = r2.x*p0 + r2.y*p1 + r2.z*p2 + r2.w*p3;
        float q3 = r3.x*p0 + r3.y*p1 + r3.z*p2 + r3.w*p3;
        p0 = q0; p1 = q1; p2 = q2; p3 = q3;
        if (more) { r0 = n0; r1 = n1; r2 = n2; r3 = n3; }
    }
}

// ---------------- K5: rotated[t] = local[t] @ (P_prev @ v[t]) ----------------
__global__ void rotate_kernel() {
    int tid = blockIdx.x*blockDim.x + threadIdx.x;   // chain-major
    if (tid >= CHAINS*Tt) return;
    int t     = tid & (Tt-1);
    int chain = tid >> 12;
    int b     = chain >> 4;
    int h     = chain & 15;
    int n     = b*Tt + t;
    int chunk = t / CHUNK;

    float4 v = *(const float4*)(g_SV + (size_t)n*NCOLS1 + VOFF + h*Nn);
    const float* P = g_Pprev + ((size_t)chain*NCHUNK + chunk)*16;
    float u0 = P[ 0]*v.x + P[ 1]*v.y + P[ 2]*v.z + P[ 3]*v.w;
    float u1 = P[ 4]*v.x + P[ 5]*v.y + P[ 6]*v.z + P[ 7]*v.w;
    float u2 = P[ 8]*v.x + P[ 9]*v.y + P[10]*v.z + P[11]*v.w;
    float u3 = P[12]*v.x + P[13]*v.y + P[14]*v.z + P[15]*v.w;

    const float4* L = (const float4*)(g_L + (size_t)tid*16);
    float4 l0 = L[0], l1 = L[1], l2 = L[2], l3 = L[3];
    float r0 = l0.x*u0 + l0.y*u1 + l0.z*u2 + l0.w*u3;
    float r1 = l1.x*u0 + l1.y*u1 + l1.z*u2 + l1.w*u3;
    float r2 = l2.x*u0 + l2.y*u1 + l2.z*u2 + l2.w*u3;
    float r3 = l3.x*u0 + l3.y*u1 + l3.z*u2 + l3.w*u3;

    *(float4*)(g_Rot + (size_t)n*HN + h*Nn) = make_float4(r0, r1, r2, r3);
}

// ---------------- launcher ----------------
extern "C" void kernel_launch(void* const* d_in, const int* in_sizes, int n_in,
                              void* d_out, int out_size) {
    const float* x     = (const float*)d_in[0];
    const float* Wskew = (const float*)d_in[1];
    const float* Wv    = (const float*)d_in[2];
    const float* Wo    = (const float*)d_in[3];
    float* out = (float*)d_out;

    concat_w_kernel<<<(D_MODEL*NCOLS1 + 255)/256, 256>>>(Wskew, Wv);
    gemm1_kernel<<<dim3(NCOLS1/32, NROWS/128), 128>>>(x);
    expm_kernel<<<(CHAINS*Tt)/256, 256>>>();
    scan_local_kernel<<<(CHAINS*NCHUNK*4)/256, 256>>>();
    prefix_kernel<<<1, 256>>>();
    rotate_kernel<<<(CHAINS*Tt)/256, 256>>>();
    gemm2_kernel<<<dim3(D_MODEL/32, NROWS/128), 128>>>(Wo, out);
}